// round 1
// baseline (speedup 1.0000x reference)
#include <cuda_runtime.h>
#include <cuda_bf16.h>
#include <math.h>

// Problem constants (fixed by the dataset)
#define NMAX 50000
#define EMAX 800000

// ---------------- device scratch (no allocations allowed) ----------------
__device__ float g_A[(size_t)NMAX * 384];   // layer-0 [Tx0|Tx1|Tx2]
__device__ float g_Bb[(size_t)NMAX * 384];  // layer-1 [Tx0|Tx1|Tx2]
__device__ float g_T[(size_t)NMAX * 128];   // elu(h@P1+pb1)
__device__ int   g_deg[NMAX];               // out-degree (segment_sum over src)
__device__ int   g_cnt[NMAX];               // in-degree  (CSR by dst)
__device__ int   g_rowptr[NMAX + 1];
__device__ int   g_cursor[NMAX];
__device__ float g_dinv[NMAX];
__device__ int   g_csr_src[EMAX];
__device__ float g_csr_norm[EMAX];

// ---------------- small kernels ----------------
__global__ void zero_kernel(int n) {
    int i = blockIdx.x * blockDim.x + threadIdx.x;
    if (i < n) { g_deg[i] = 0; g_cnt[i] = 0; }
}

__global__ void count_kernel(const int* __restrict__ src, const int* __restrict__ dst, int E) {
    int e = blockIdx.x * blockDim.x + threadIdx.x;
    if (e < E) {
        atomicAdd(&g_deg[src[e]], 1);
        atomicAdd(&g_cnt[dst[e]], 1);
    }
}

__global__ void dinv_kernel(int n) {
    int i = blockIdx.x * blockDim.x + threadIdx.x;
    if (i < n) {
        int d = g_deg[i];
        g_dinv[i] = (d > 0) ? rsqrtf((float)d) : 0.0f;
    }
}

// exclusive scan of g_cnt -> g_rowptr / g_cursor (single block, 1024 threads)
__global__ void scan_kernel(int n, int E) {
    __shared__ int sh[1024];
    const int T = 1024;
    int tid = threadIdx.x;
    int ch = (n + T - 1) / T;
    int start = tid * ch;
    int s = 0;
    for (int i = 0; i < ch; i++) {
        int idx = start + i;
        if (idx < n) s += g_cnt[idx];
    }
    sh[tid] = s;
    __syncthreads();
    for (int off = 1; off < T; off <<= 1) {
        int v = (tid >= off) ? sh[tid - off] : 0;
        __syncthreads();
        sh[tid] += v;
        __syncthreads();
    }
    int run = (tid > 0) ? sh[tid - 1] : 0;
    for (int i = 0; i < ch; i++) {
        int idx = start + i;
        if (idx < n) {
            g_rowptr[idx] = run;
            g_cursor[idx] = run;
            run += g_cnt[idx];
        }
    }
    if (tid == 0) g_rowptr[n] = E;
}

__global__ void scatter_kernel(const int* __restrict__ src, const int* __restrict__ dst, int E) {
    int e = blockIdx.x * blockDim.x + threadIdx.x;
    if (e < E) {
        int s = src[e], d = dst[e];
        int pos = atomicAdd(&g_cursor[d], 1);
        g_csr_src[pos] = s;
        g_csr_norm[pos] = -g_dinv[s] * g_dinv[d];
    }
}

// build x = [emb_id | emb_len | emb_lng | emb_lat | vis] into g_A[:,0:128] (stride 384)
__global__ void build_x_kernel(const int* __restrict__ attr, const float* __restrict__ vis,
                               const float* __restrict__ e_len, const float* __restrict__ e_id,
                               const float* __restrict__ e_lng, const float* __restrict__ e_lat,
                               int n) {
    int idx = blockIdx.x * blockDim.x + threadIdx.x;
    if (idx >= n * 32) return;
    int node = idx >> 5;
    int c = (idx & 31) * 4;
    const int* a = attr + node * 4;
    float4 v;
    if (c < 16)       v = *(const float4*)(e_id  + (size_t)a[1] * 16 + c);
    else if (c < 32)  v = *(const float4*)(e_len + (size_t)a[0] * 16 + (c - 16));
    else if (c < 48)  v = *(const float4*)(e_lng + (size_t)a[2] * 16 + (c - 32));
    else if (c < 64)  v = *(const float4*)(e_lat + (size_t)a[3] * 16 + (c - 48));
    else              v = *(const float4*)(vis   + (size_t)node * 64 + (c - 64));
    *(float4*)(g_A + (size_t)node * 384 + c) = v;
}

// CSR propagation: warp per destination node.
// mode 0: out = sum(norm * in[src])            (Tx1 = prop(Tx0))
// mode 1: out = 2*sum(norm * in[src]) - buf[:,0:128]   (Tx2 = 2*prop(Tx1) - Tx0)
__global__ void prop_kernel(float* __restrict__ buf, int in_off, int out_off, int mode, int n) {
    int g = (blockIdx.x * blockDim.x + threadIdx.x) >> 5;
    if (g >= n) return;
    int lane = threadIdx.x & 31;
    int c = lane * 4;
    int beg = g_rowptr[g], end = g_rowptr[g + 1];
    float4 acc = make_float4(0.f, 0.f, 0.f, 0.f);
    for (int i = beg; i < end; i++) {
        int s = g_csr_src[i];
        float nm = g_csr_norm[i];
        float4 v = *(const float4*)(buf + (size_t)s * 384 + in_off + c);
        acc.x = fmaf(nm, v.x, acc.x);
        acc.y = fmaf(nm, v.y, acc.y);
        acc.z = fmaf(nm, v.z, acc.z);
        acc.w = fmaf(nm, v.w, acc.w);
    }
    if (mode == 1) {
        float4 p = *(const float4*)(buf + (size_t)g * 384 + c);
        acc.x = 2.f * acc.x - p.x;
        acc.y = 2.f * acc.y - p.y;
        acc.z = 2.f * acc.z - p.z;
        acc.w = 2.f * acc.w - p.w;
    }
    *(float4*)(buf + (size_t)g * 384 + out_off + c) = acc;
}

// Tiled fp32 GEMM: C[M, ncols] = act(A[M,K] @ B[K,ncols] + bias), 64x64 tile, 4x4 microtile.
// act: 0 = none, 1 = relu, 2 = elu
__global__ void gemm_kernel(const float* __restrict__ A, int lda,
                            const float* __restrict__ Bw, int ldb,
                            const float* __restrict__ bias,
                            float* __restrict__ C, int ldc,
                            int M, int Kdim, int act) {
    __shared__ float As[16][68];
    __shared__ float Bs[16][68];
    int t  = threadIdx.x;          // 256 threads
    int m0 = blockIdx.x * 64;
    int n0 = blockIdx.y * 64;
    int ar  = t >> 2;              // 0..63  (A tile row)
    int akq = (t & 3) * 4;         // k quad within tile
    int bk  = t >> 4;              // 0..15  (B tile k)
    int bnq = (t & 15) * 4;        // n quad
    int ty = t >> 4, tx = t & 15;
    float acc[4][4] = {};

    for (int k0 = 0; k0 < Kdim; k0 += 16) {
        int row = m0 + ar;
        float4 a4 = make_float4(0.f, 0.f, 0.f, 0.f);
        if (row < M) a4 = *(const float4*)(A + (size_t)row * lda + k0 + akq);
        As[akq + 0][ar] = a4.x;
        As[akq + 1][ar] = a4.y;
        As[akq + 2][ar] = a4.z;
        As[akq + 3][ar] = a4.w;
        *(float4*)(&Bs[bk][bnq]) = *(const float4*)(Bw + (size_t)(k0 + bk) * ldb + n0 + bnq);
        __syncthreads();
#pragma unroll
        for (int k = 0; k < 16; k++) {
            float4 av = *(const float4*)(&As[k][ty * 4]);
            float4 bv = *(const float4*)(&Bs[k][tx * 4]);
            float a[4] = {av.x, av.y, av.z, av.w};
            float b[4] = {bv.x, bv.y, bv.z, bv.w};
#pragma unroll
            for (int i = 0; i < 4; i++)
#pragma unroll
                for (int j = 0; j < 4; j++)
                    acc[i][j] = fmaf(a[i], b[j], acc[i][j]);
        }
        __syncthreads();
    }

#pragma unroll
    for (int i = 0; i < 4; i++) {
        int row = m0 + ty * 4 + i;
        if (row < M) {
#pragma unroll
            for (int j = 0; j < 4; j++) {
                int col = n0 + tx * 4 + j;
                float v = acc[i][j] + bias[col];
                if (act == 1)      v = fmaxf(v, 0.f);
                else if (act == 2) v = (v > 0.f) ? v : expm1f(v);
                C[(size_t)row * ldc + col] = v;
            }
        }
    }
}

// ---------------- launch ----------------
extern "C" void kernel_launch(void* const* d_in, const int* in_sizes, int n_in,
                              void* d_out, int out_size) {
    const int*   edge  = (const int*)d_in[0];
    const int*   attr  = (const int*)d_in[1];
    const float* vis   = (const float*)d_in[2];
    const float* e_len = (const float*)d_in[3];
    const float* e_id  = (const float*)d_in[4];
    const float* e_lng = (const float*)d_in[5];
    const float* e_lat = (const float*)d_in[6];
    const float* W0    = (const float*)d_in[7];   // [3,128,128] == [384,128]
    const float* b0    = (const float*)d_in[8];
    const float* W1    = (const float*)d_in[9];
    const float* b1    = (const float*)d_in[10];
    const float* P1    = (const float*)d_in[11];
    const float* pb1   = (const float*)d_in[12];
    const float* P2    = (const float*)d_in[13];
    const float* pb2   = (const float*)d_in[14];
    float* out = (float*)d_out;

    const int E = in_sizes[0] / 2;
    const int N = in_sizes[1] / 4;
    const int* src = edge;
    const int* dst = edge + E;

    float *pA, *pB, *pT;
    cudaGetSymbolAddress((void**)&pA, g_A);
    cudaGetSymbolAddress((void**)&pB, g_Bb);
    cudaGetSymbolAddress((void**)&pT, g_T);

    const int TB = 256;
    dim3 gemm_grid2((N + 63) / 64, 2);
    dim3 gemm_grid1((N + 63) / 64, 1);

    // --- graph preprocessing (CSR by dst + norms) ---
    zero_kernel<<<(N + TB - 1) / TB, TB>>>(N);
    count_kernel<<<(E + TB - 1) / TB, TB>>>(src, dst, E);
    dinv_kernel<<<(N + TB - 1) / TB, TB>>>(N);
    scan_kernel<<<1, 1024>>>(N, E);
    scatter_kernel<<<(E + TB - 1) / TB, TB>>>(src, dst, E);

    // --- x features into g_A[:,0:128] ---
    build_x_kernel<<<(N * 32 + TB - 1) / TB, TB>>>(attr, vis, e_len, e_id, e_lng, e_lat, N);

    // --- layer 0: Tx1, Tx2, fused GEMM (K=384) -> h0 = relu(...) into g_Bb[:,0:128] ---
    prop_kernel<<<(N * 32 + TB - 1) / TB, TB>>>(pA, 0, 128, 0, N);
    prop_kernel<<<(N * 32 + TB - 1) / TB, TB>>>(pA, 128, 256, 1, N);
    gemm_kernel<<<gemm_grid2, TB>>>(pA, 384, W0, 128, b0, pB, 384, N, 384, 1);

    // --- layer 1: props on g_Bb, GEMM -> h into d_out[0 : N*128] ---
    prop_kernel<<<(N * 32 + TB - 1) / TB, TB>>>(pB, 0, 128, 0, N);
    prop_kernel<<<(N * 32 + TB - 1) / TB, TB>>>(pB, 128, 256, 1, N);
    gemm_kernel<<<gemm_grid2, TB>>>(pB, 384, W1, 128, b1, out, 128, N, 384, 1);

    // --- projection head: t = elu(h@P1+pb1); z = t@P2+pb2 -> d_out[N*128 : ] ---
    gemm_kernel<<<gemm_grid2, TB>>>(out, 128, P1, 128, pb1, pT, 128, N, 128, 2);
    gemm_kernel<<<gemm_grid1, TB>>>(pT, 128, P2, 64, pb2, out + (size_t)N * 128, 64, N, 128, 0);
}

// round 3
// speedup vs baseline: 1.2966x; 1.2966x over previous
#include <cuda_runtime.h>
#include <cuda_bf16.h>
#include <math.h>
#include <stdint.h>

#define NMAX 50000
#define EMAX 800000

// ---------------- device scratch ----------------
__device__ float g_A[(size_t)NMAX * 384];   // layer-0 [Tx0|Tx1|Tx2]
__device__ float g_Bb[(size_t)NMAX * 384];  // layer-1 [Tx0|Tx1|Tx2]
__device__ float g_T[(size_t)NMAX * 128];   // elu(h@P1+pb1)
__device__ int   g_deg[NMAX];
__device__ int   g_cnt[NMAX];
__device__ int   g_rowptr[NMAX + 1];
__device__ int   g_cursor[NMAX];
__device__ float g_dinv[NMAX];
__device__ int   g_csr_src[EMAX];
__device__ float g_csr_norm[EMAX];
__device__ int   g_blksum[256];
// packed weights, fragment order: [n][K] u32 where per n-row: ks*16 + t*4 + {b0h,b1h,b0l,b1l}
__device__ uint32_t g_Wp0[128 * 384];
__device__ uint32_t g_Wp1[128 * 384];
__device__ uint32_t g_Pp1[128 * 128];
__device__ uint32_t g_Pp2[64 * 128];

// ---------------- preprocessing kernels ----------------
__global__ void zero_kernel(int n) {
    int i = blockIdx.x * blockDim.x + threadIdx.x;
    if (i < n) { g_deg[i] = 0; g_cnt[i] = 0; }
}

__global__ void count_kernel(const int* __restrict__ src, const int* __restrict__ dst, int E) {
    int e = blockIdx.x * blockDim.x + threadIdx.x;
    if (e < E) {
        atomicAdd(&g_deg[src[e]], 1);
        atomicAdd(&g_cnt[dst[e]], 1);
    }
}

__global__ void dinv_kernel(int n) {
    int i = blockIdx.x * blockDim.x + threadIdx.x;
    if (i < n) {
        int d = g_deg[i];
        g_dinv[i] = (d > 0) ? rsqrtf((float)d) : 0.0f;
    }
}

__global__ void scan_phaseA(int n) {
    __shared__ int sh[256];
    int t = threadIdx.x;
    int i = blockIdx.x * 256 + t;
    sh[t] = (i < n) ? g_cnt[i] : 0;
    __syncthreads();
    for (int off = 128; off > 0; off >>= 1) {
        if (t < off) sh[t] += sh[t + off];
        __syncthreads();
    }
    if (t == 0) g_blksum[blockIdx.x] = sh[0];
}

__global__ void scan_phaseB(int nb) {
    __shared__ int sh[256];
    int t = threadIdx.x;
    int orig = (t < nb) ? g_blksum[t] : 0;
    sh[t] = orig;
    __syncthreads();
    for (int off = 1; off < 256; off <<= 1) {
        int v = (t >= off) ? sh[t - off] : 0;
        __syncthreads();
        sh[t] += v;
        __syncthreads();
    }
    if (t < nb) g_blksum[t] = sh[t] - orig;   // exclusive
}

__global__ void scan_phaseC(int n, int E) {
    __shared__ int sh[256];
    int t = threadIdx.x;
    int i = blockIdx.x * 256 + t;
    int v = (i < n) ? g_cnt[i] : 0;
    sh[t] = v;
    __syncthreads();
    for (int off = 1; off < 256; off <<= 1) {
        int u = (t >= off) ? sh[t - off] : 0;
        __syncthreads();
        sh[t] += u;
        __syncthreads();
    }
    int excl = sh[t] - v + g_blksum[blockIdx.x];
    if (i < n) { g_rowptr[i] = excl; g_cursor[i] = excl; }
    if (i == 0) g_rowptr[n] = E;
}

__global__ void scatter_kernel(const int* __restrict__ src, const int* __restrict__ dst, int E) {
    int e = blockIdx.x * blockDim.x + threadIdx.x;
    if (e < E) {
        int s = src[e], d = dst[e];
        int pos = atomicAdd(&g_cursor[d], 1);
        g_csr_src[pos] = s;
        g_csr_norm[pos] = -g_dinv[s] * g_dinv[d];
    }
}

// Pack W[K, Nc] (row-major, k-major) into fragment-order hi/lo bf16x2 array:
// P[n*K + ks*16 + t*4 + j], j in {b0h, b1h, b0l, b1l}
//   b0: k = ks*16 + 2t, 2t+1 ;  b1: k = ks*16 + 2t+8, 2t+9
__global__ void pack_weights(const float* __restrict__ W, uint32_t* __restrict__ P,
                             int K, int Nc) {
    int idx = blockIdx.x * blockDim.x + threadIdx.x;
    int total = Nc * K;
    if (idx >= total) return;
    int j  = idx & 3;
    int t  = (idx >> 2) & 3;
    int rem = idx >> 4;
    int nks = K >> 4;
    int ks = rem % nks;
    int n  = rem / nks;
    int kb = ks * 16 + 2 * t + ((j & 1) ? 8 : 0);
    float v0 = W[(size_t)kb * Nc + n];
    float v1 = W[(size_t)(kb + 1) * Nc + n];
    if (j >= 2) {   // lo residual
        v0 -= __bfloat162float(__float2bfloat16_rn(v0));
        v1 -= __bfloat162float(__float2bfloat16_rn(v1));
    }
    __nv_bfloat162 p = __floats2bfloat162_rn(v0, v1);  // x (low) = v0
    P[idx] = *(uint32_t*)&p;
}

// build x = [emb_id | emb_len | emb_lng | emb_lat | vis] into g_A[:,0:128] (stride 384)
__global__ void build_x_kernel(const int* __restrict__ attr, const float* __restrict__ vis,
                               const float* __restrict__ e_len, const float* __restrict__ e_id,
                               const float* __restrict__ e_lng, const float* __restrict__ e_lat,
                               int n) {
    int idx = blockIdx.x * blockDim.x + threadIdx.x;
    if (idx >= n * 32) return;
    int node = idx >> 5;
    int c = (idx & 31) * 4;
    const int* a = attr + node * 4;
    float4 v;
    if (c < 16)       v = *(const float4*)(e_id  + (size_t)a[1] * 16 + c);
    else if (c < 32)  v = *(const float4*)(e_len + (size_t)a[0] * 16 + (c - 16));
    else if (c < 48)  v = *(const float4*)(e_lng + (size_t)a[2] * 16 + (c - 32));
    else if (c < 64)  v = *(const float4*)(e_lat + (size_t)a[3] * 16 + (c - 48));
    else              v = *(const float4*)(vis   + (size_t)node * 64 + (c - 64));
    *(float4*)(g_A + (size_t)node * 384 + c) = v;
}

// CSR propagation: warp per destination node.
__global__ void prop_kernel(float* __restrict__ buf, int in_off, int out_off, int mode, int n) {
    int g = (blockIdx.x * blockDim.x + threadIdx.x) >> 5;
    if (g >= n) return;
    int lane = threadIdx.x & 31;
    int c = lane * 4;
    int beg = g_rowptr[g], end = g_rowptr[g + 1];
    float4 acc = make_float4(0.f, 0.f, 0.f, 0.f);
    for (int i = beg; i < end; i++) {
        int s = g_csr_src[i];
        float nm = g_csr_norm[i];
        float4 v = *(const float4*)(buf + (size_t)s * 384 + in_off + c);
        acc.x = fmaf(nm, v.x, acc.x);
        acc.y = fmaf(nm, v.y, acc.y);
        acc.z = fmaf(nm, v.z, acc.z);
        acc.w = fmaf(nm, v.w, acc.w);
    }
    if (mode == 1) {
        float4 p = *(const float4*)(buf + (size_t)g * 384 + c);
        acc.x = 2.f * acc.x - p.x;
        acc.y = 2.f * acc.y - p.y;
        acc.z = 2.f * acc.z - p.z;
        acc.w = 2.f * acc.w - p.w;
    }
    *(float4*)(buf + (size_t)g * 384 + out_off + c) = acc;
}

// ---------------- mma.sync bf16 split-precision GEMM ----------------
__device__ __forceinline__ void mma_bf16(float* c, uint32_t a0, uint32_t a1, uint32_t a2,
                                         uint32_t a3, uint32_t b0, uint32_t b1) {
    asm volatile(
        "mma.sync.aligned.m16n8k16.row.col.f32.bf16.bf16.f32 "
        "{%0,%1,%2,%3}, {%4,%5,%6,%7}, {%8,%9}, {%0,%1,%2,%3};"
        : "+f"(c[0]), "+f"(c[1]), "+f"(c[2]), "+f"(c[3])
        : "r"(a0), "r"(a1), "r"(a2), "r"(a3), "r"(b0), "r"(b1));
}

__device__ __forceinline__ uint32_t pack_hi2(float x, float y) {
    __nv_bfloat162 p = __floats2bfloat162_rn(x, y);
    return *(uint32_t*)&p;
}
__device__ __forceinline__ uint32_t pack_lo2(float x, float y) {
    float rx = x - __bfloat162float(__float2bfloat16_rn(x));
    float ry = y - __bfloat162float(__float2bfloat16_rn(y));
    __nv_bfloat162 p = __floats2bfloat162_rn(rx, ry);
    return *(uint32_t*)&p;
}

// C[M, N=8*NT] = act(A[M,K] @ W + bias). Warp = 16 exclusive rows, CTA = 128 rows.
// act: 0 none, 1 relu, 2 elu
template <int NT>
__global__ __launch_bounds__(256) void mma_gemm_kernel(
    const float* __restrict__ A, int lda,
    const uint32_t* __restrict__ Wp,   // packed [n][K] u32 fragment order
    const float* __restrict__ bias,
    float* __restrict__ C, int ldc,
    int M, int K, int act)
{
    int tid = threadIdx.x;
    int w = tid >> 5, lane = tid & 31;
    int gid = lane >> 2, tig = lane & 3;
    int r0 = blockIdx.x * 128 + w * 16 + gid;   // rows r0, r0+8
    bool v0 = r0 < M, v1 = (r0 + 8) < M;

    float acc[NT][4];
#pragma unroll
    for (int i = 0; i < NT; i++) { acc[i][0] = acc[i][1] = acc[i][2] = acc[i][3] = 0.f; }

    const float* a_base = A + (size_t)r0 * lda + 2 * tig;
    const int nks = K >> 4;

    for (int ks = 0; ks < nks; ks++) {
        int k0 = ks << 4;
        float2 p00 = v0 ? *(const float2*)(a_base + k0)               : make_float2(0.f, 0.f);
        float2 p10 = v1 ? *(const float2*)(a_base + 8 * lda + k0)     : make_float2(0.f, 0.f);
        float2 p01 = v0 ? *(const float2*)(a_base + k0 + 8)           : make_float2(0.f, 0.f);
        float2 p11 = v1 ? *(const float2*)(a_base + 8 * lda + k0 + 8) : make_float2(0.f, 0.f);
        uint32_t ah0 = pack_hi2(p00.x, p00.y), ah1 = pack_hi2(p10.x, p10.y);
        uint32_t ah2 = pack_hi2(p01.x, p01.y), ah3 = pack_hi2(p11.x, p11.y);
        uint32_t al0 = pack_lo2(p00.x, p00.y), al1 = pack_lo2(p10.x, p10.y);
        uint32_t al2 = pack_lo2(p01.x, p01.y), al3 = pack_lo2(p11.x, p11.y);

        const uint32_t* wp = Wp + (size_t)gid * K + k0 + tig * 4;
#pragma unroll
        for (int nt = 0; nt < NT; nt++) {
            uint4 q = *(const uint4*)(wp + (size_t)nt * 8 * K);
            mma_bf16(acc[nt], ah0, ah1, ah2, ah3, q.x, q.y);   // hi * hi
            mma_bf16(acc[nt], ah0, ah1, ah2, ah3, q.z, q.w);   // hi * lo
            mma_bf16(acc[nt], al0, al1, al2, al3, q.x, q.y);   // lo * hi
        }
    }

    // epilogue
#pragma unroll
    for (int nt = 0; nt < NT; nt++) {
        int col = nt * 8 + 2 * tig;
        float b0 = bias[col], b1 = bias[col + 1];
        float e0 = acc[nt][0] + b0, e1 = acc[nt][1] + b1;
        float e2 = acc[nt][2] + b0, e3 = acc[nt][3] + b1;
        if (act == 1) {
            e0 = fmaxf(e0, 0.f); e1 = fmaxf(e1, 0.f);
            e2 = fmaxf(e2, 0.f); e3 = fmaxf(e3, 0.f);
        } else if (act == 2) {
            if (e0 < 0.f) e0 = expm1f(e0);
            if (e1 < 0.f) e1 = expm1f(e1);
            if (e2 < 0.f) e2 = expm1f(e2);
            if (e3 < 0.f) e3 = expm1f(e3);
        }
        if (v0) *(float2*)(C + (size_t)r0 * ldc + col) = make_float2(e0, e1);
        if (v1) *(float2*)(C + (size_t)(r0 + 8) * ldc + col) = make_float2(e2, e3);
    }
}

// ---------------- launch ----------------
extern "C" void kernel_launch(void* const* d_in, const int* in_sizes, int n_in,
                              void* d_out, int out_size) {
    const int*   edge  = (const int*)d_in[0];
    const int*   attr  = (const int*)d_in[1];
    const float* vis   = (const float*)d_in[2];
    const float* e_len = (const float*)d_in[3];
    const float* e_id  = (const float*)d_in[4];
    const float* e_lng = (const float*)d_in[5];
    const float* e_lat = (const float*)d_in[6];
    const float* W0    = (const float*)d_in[7];   // [3,128,128] == [384,128]
    const float* b0    = (const float*)d_in[8];
    const float* W1    = (const float*)d_in[9];
    const float* b1    = (const float*)d_in[10];
    const float* P1    = (const float*)d_in[11];
    const float* pb1   = (const float*)d_in[12];
    const float* P2    = (const float*)d_in[13];
    const float* pb2   = (const float*)d_in[14];
    float* out = (float*)d_out;

    const int E = in_sizes[0] / 2;
    const int N = in_sizes[1] / 4;
    const int* src = edge;
    const int* dst = edge + E;

    float *pA, *pB, *pT;
    uint32_t *pWp0, *pWp1, *pPp1, *pPp2;
    cudaGetSymbolAddress((void**)&pA, g_A);
    cudaGetSymbolAddress((void**)&pB, g_Bb);
    cudaGetSymbolAddress((void**)&pT, g_T);
    cudaGetSymbolAddress((void**)&pWp0, g_Wp0);
    cudaGetSymbolAddress((void**)&pWp1, g_Wp1);
    cudaGetSymbolAddress((void**)&pPp1, g_Pp1);
    cudaGetSymbolAddress((void**)&pPp2, g_Pp2);

    const int TB = 256;
    const int nb = (N + 255) / 256;
    const int gtiles = (N + 127) / 128;

    // --- graph preprocessing (CSR by dst + norms) ---
    zero_kernel<<<(N + TB - 1) / TB, TB>>>(N);
    count_kernel<<<(E + TB - 1) / TB, TB>>>(src, dst, E);
    dinv_kernel<<<(N + TB - 1) / TB, TB>>>(N);
    scan_phaseA<<<nb, 256>>>(N);
    scan_phaseB<<<1, 256>>>(nb);
    scan_phaseC<<<nb, 256>>>(N, E);
    scatter_kernel<<<(E + TB - 1) / TB, TB>>>(src, dst, E);

    // --- weight packing (tiny) ---
    pack_weights<<<(128 * 384 + TB - 1) / TB, TB>>>(W0, pWp0, 384, 128);
    pack_weights<<<(128 * 384 + TB - 1) / TB, TB>>>(W1, pWp1, 384, 128);
    pack_weights<<<(128 * 128 + TB - 1) / TB, TB>>>(P1, pPp1, 128, 128);
    pack_weights<<<(64 * 128  + TB - 1) / TB, TB>>>(P2, pPp2, 128, 64);

    // --- x features into g_A[:,0:128] ---
    build_x_kernel<<<(N * 32 + TB - 1) / TB, TB>>>(attr, vis, e_len, e_id, e_lng, e_lat, N);

    // --- layer 0 ---
    prop_kernel<<<(N * 32 + TB - 1) / TB, TB>>>(pA, 0, 128, 0, N);
    prop_kernel<<<(N * 32 + TB - 1) / TB, TB>>>(pA, 128, 256, 1, N);
    mma_gemm_kernel<16><<<gtiles, 256>>>(pA, 384, pWp0, b0, pB, 384, N, 384, 1);

    // --- layer 1 ---
    prop_kernel<<<(N * 32 + TB - 1) / TB, TB>>>(pB, 0, 128, 0, N);
    prop_kernel<<<(N * 32 + TB - 1) / TB, TB>>>(pB, 128, 256, 1, N);
    mma_gemm_kernel<16><<<gtiles, 256>>>(pB, 384, pWp1, b1, out, 128, N, 384, 1);

    // --- projection head ---
    mma_gemm_kernel<16><<<gtiles, 256>>>(out, 128, pPp1, pb1, pT, 128, N, 128, 2);
    mma_gemm_kernel<8><<<gtiles, 256>>>(pT, 128, pPp2, pb2, out + (size_t)N * 128, 64, N, 128, 0);
}